// round 16
// baseline (speedup 1.0000x reference)
#include <cuda_runtime.h>
#include <cuda_fp16.h>

#define N_NODES   1000000
#define N_EDGES   2000000
#define N_FEAT    11
#define HPAD      16           // fp16 halves per padded u row (32 bytes)
#define HIDDEN    64
#define N_CLASSES 19
#define BATCH     128

#define SPLIT 16
#define TILE  256
#define NB_SCAN 977            // ceil(1M / 1024)
#define FIN_NODES 256

typedef unsigned long long ull;

// ---- scratch (device globals; no allocs) ----
__device__ __align__(16) int    g_count[N_NODES];
__device__ __align__(16) int    g_rowptr[N_NODES + 4];   // after fill: rowptr[i] = end of node i
__device__ __align__(16) int    g_srcs[N_EDGES];
__device__ __align__(16) float  g_dinv[N_NODES];
__device__ __align__(16) __half g_xpad[N_NODES * HPAD];  // u = x * dinv[row], fp16, 32B rows
__device__ float g_pooled[BATCH * HIDDEN];
__device__ int   g_bnd[BATCH + 1];
__device__ __align__(16) ull  g_state[NB_SCAN];          // decoupled-lookback state
__device__ int   g_ticket;

__device__ __forceinline__ ull fma2(ull a, ull b, ull c) {
    ull d; asm("fma.rn.f32x2 %0, %1, %2, %3;" : "=l"(d) : "l"(a), "l"(b), "l"(c)); return d;
}
__device__ __forceinline__ ull pack2(float lo, float hi) {
    ull d; asm("mov.b64 %0, {%1, %2};" : "=l"(d) : "f"(lo), "f"(hi)); return d;
}
__device__ __forceinline__ void unpack2(float& lo, float& hi, ull v) {
    asm("mov.b64 {%0, %1}, %2;" : "=f"(lo), "=f"(hi) : "l"(v));
}

// ---- fused histogram (in-degree) + batch segment boundaries ----
__global__ void hist_bnd_kernel(const int* __restrict__ ei,
                                const int* __restrict__ batch) {
    int q = blockIdx.x * blockDim.x + threadIdx.x;
    if (q < N_EDGES / 4) {
        int4 cc = ((const int4*)(ei + N_EDGES))[q];
        if ((unsigned)cc.x < N_NODES) atomicAdd(&g_count[cc.x], 1);
        if ((unsigned)cc.y < N_NODES) atomicAdd(&g_count[cc.y], 1);
        if ((unsigned)cc.z < N_NODES) atomicAdd(&g_count[cc.z], 1);
        if ((unsigned)cc.w < N_NODES) atomicAdd(&g_count[cc.w], 1);
    }
    if (q < N_NODES / 4) {
        int i0 = q * 4;
        int4 v = ((const int4*)batch)[q];
        int prev = (i0 == 0) ? -1 : batch[i0 - 1];
        int vals[4] = {v.x, v.y, v.z, v.w};
        #pragma unroll
        for (int t = 0; t < 4; t++) {
            int cur = vals[t];
            for (int k = prev + 1; k <= cur && k <= BATCH; k++) g_bnd[k] = i0 + t;
            prev = cur;
        }
        if (i0 + 4 == N_NODES) {
            for (int k = prev + 1; k <= BATCH; k++) g_bnd[k] = N_NODES;
        }
    }
}

// ---- single-pass decoupled-lookback scan: g_count -> g_rowptr (exclusive) ----
// state word: status in bits [62:64): 1 = aggregate ready, 2 = prefix ready.
__global__ void __launch_bounds__(256)
scan_kernel() {
    __shared__ int s_bid;
    __shared__ int wsum[8];
    __shared__ int s_excl;
    int tid = threadIdx.x, lane = tid & 31, wid = tid >> 5;

    if (tid == 0) s_bid = atomicAdd(&g_ticket, 1);
    __syncthreads();
    int bid = s_bid;

    int idx4 = bid * 256 + tid;
    int4 v = (idx4 * 4 < N_NODES) ? ((const int4*)g_count)[idx4] : make_int4(0,0,0,0);
    int s = v.x + v.y + v.z + v.w;
    int incl = s;
    #pragma unroll
    for (int o = 1; o < 32; o <<= 1) {
        int t = __shfl_up_sync(0xffffffffu, incl, o);
        if (lane >= o) incl += t;
    }
    if (lane == 31) wsum[wid] = incl;
    __syncthreads();
    int woff = 0, total = 0;
    #pragma unroll
    for (int w = 0; w < 8; w++) {
        if (w < wid) woff += wsum[w];
        total += wsum[w];
    }

    // lookback (thread 0)
    if (tid == 0) {
        if (bid == 0) {
            s_excl = 0;
            __threadfence();
            atomicExch(&g_state[0], (2ull << 62) | (unsigned)total);
        } else {
            __threadfence();
            atomicExch(&g_state[bid], (1ull << 62) | (unsigned)total);
            long long running = 0;
            int j = bid - 1;
            while (j >= 0) {
                ull st = atomicOr(&g_state[j], 0ull);
                ull status = st >> 62;
                if (status == 0) continue;                 // spin
                running += (long long)(st & 0x3FFFFFFFFFFFFFFFull);
                if (status == 2) break;
                j--;
            }
            s_excl = (int)running;
            __threadfence();
            atomicExch(&g_state[bid], (2ull << 62) | (unsigned)(running + total));
        }
    }
    __syncthreads();

    int base = s_excl + woff + incl - s;   // global exclusive for this thread's 4 elems
    if (idx4 * 4 < N_NODES) {
        int4 r;
        r.x = base; r.y = base + v.x; r.z = r.y + v.y; r.w = r.z + v.z;
        ((int4*)g_rowptr)[idx4] = r;
    }
}

// ---- dinv + fp16 pad (u = x * dinv); needs only g_count ----
__global__ void __launch_bounds__(256)
dinv_pad_kernel(const float* __restrict__ x) {
    __shared__ float sx[FIN_NODES * N_FEAT];   // 11 KB
    __shared__ float sdv[FIN_NODES];
    int base = blockIdx.x * FIN_NODES;
    int cnt  = min(FIN_NODES, N_NODES - base);
    int tid  = threadIdx.x;

    {
        const float4* xs = (const float4*)(x + (long long)base * N_FEAT);
        float4* s4 = (float4*)sx;
        int nv = cnt * N_FEAT / 4;
        for (int i = tid; i < nv; i += FIN_NODES) s4[i] = xs[i];
    }
    if (tid < cnt / 4) {
        int q = base / 4 + tid;
        int4 c4 = ((const int4*)g_count)[q];
        float4 dv;
        dv.x = (c4.x > 0) ? rsqrtf((float)c4.x) : 0.0f;
        dv.y = (c4.y > 0) ? rsqrtf((float)c4.y) : 0.0f;
        dv.z = (c4.z > 0) ? rsqrtf((float)c4.z) : 0.0f;
        dv.w = (c4.w > 0) ? rsqrtf((float)c4.w) : 0.0f;
        ((float4*)g_dinv)[q] = dv;
        *(float4*)&sdv[tid * 4] = dv;
    }
    __syncthreads();
    {
        uint4* dst = (uint4*)&g_xpad[(long long)base * HPAD];
        int nv = cnt * 2;
        for (int i = tid; i < nv; i += FIN_NODES) {
            int node = i >> 1, hi = i & 1;
            float dv = sdv[node];
            const float* a = &sx[node * N_FEAT];
            __half2 h[4];
            if (hi == 0) {
                h[0] = __floats2half2_rn(a[0]*dv, a[1]*dv);
                h[1] = __floats2half2_rn(a[2]*dv, a[3]*dv);
                h[2] = __floats2half2_rn(a[4]*dv, a[5]*dv);
                h[3] = __floats2half2_rn(a[6]*dv, a[7]*dv);
            } else {
                h[0] = __floats2half2_rn(a[8]*dv,  a[9]*dv);
                h[1] = __floats2half2_rn(a[10]*dv, 0.0f);
                h[2] = __floats2half2_rn(0.0f, 0.0f);
                h[3] = h[2];
            }
            dst[i] = *(const uint4*)h;
        }
    }
}

// ---- CSR fill: bump rowptr in place; after this rowptr[i] = end(node i) ----
__global__ void fill_kernel(const int* __restrict__ ei) {
    int q = blockIdx.x * blockDim.x + threadIdx.x;
    if (q >= N_EDGES / 4) return;
    int4 rr = ((const int4*)ei)[q];
    int4 cc = ((const int4*)(ei + N_EDGES))[q];
    #pragma unroll
    for (int k = 0; k < 4; k++) {
        int r = (k == 0) ? rr.x : (k == 1) ? rr.y : (k == 2) ? rr.z : rr.w;
        int c = (k == 0) ? cc.x : (k == 1) ? cc.y : (k == 2) ? cc.z : cc.w;
        if ((unsigned)c < N_NODES) {
            int pos = atomicAdd(&g_rowptr[c], 1);
            if ((unsigned)pos < N_EDGES) g_srcs[pos] = r;
        }
    }
}

// ---- fused CSR-gather(fp16 rows) + transform(f32x2) + ReLU + pool ----
__global__ void __launch_bounds__(256)
fused_kernel(const float* __restrict__ Wc, const float* __restrict__ bc) {
    int b     = blockIdx.x >> 4;      // SPLIT=16
    int split = blockIdx.x & 15;
    int start = g_bnd[b];
    int end   = g_bnd[b + 1];
    int total = end - start;
    int chunk = (total + SPLIT - 1) / SPLIT;
    int s0    = start + split * chunk;
    int s1    = min(s0 + chunk, end);

    __shared__ float sW[N_FEAT * HIDDEN];
    __shared__ float sb[HIDDEN];
    __shared__ __align__(16) float sxT[N_FEAT][TILE];   // feature-major tile (fp32)
    __shared__ float red[4][HIDDEN];

    for (int i = threadIdx.x; i < N_FEAT * HIDDEN; i += blockDim.x) sW[i] = Wc[i];
    if (threadIdx.x < HIDDEN) sb[threadIdx.x] = bc[threadIdx.x];
    __syncthreads();

    int j = threadIdx.x & 63;
    int s = threadIdx.x >> 6;

    ull w2[N_FEAT];
    #pragma unroll
    for (int f = 0; f < N_FEAT; f++) { float w = sW[f * HIDDEN + j]; w2[f] = pack2(w, w); }
    float bj  = sb[j];
    ull   bj2 = pack2(bj, bj);
    float acc = 0.0f;
    int   padsum = 0;

    for (int t0 = s0; t0 < s1; t0 += TILE) {
        int cnt  = min(TILE, s1 - t0);
        int cntp = (cnt + 3) & ~3;
        __syncthreads();
        if (threadIdx.x < cntp) {
            float a[N_FEAT + 1];
            #pragma unroll
            for (int f = 0; f <= N_FEAT; f++) a[f] = 0.0f;
            if (threadIdx.x < cnt) {
                int node = t0 + threadIdx.x;
                int beg = (node > 0) ? g_rowptr[node - 1] : 0;
                int fin = g_rowptr[node];
                for (int e = beg; e < fin; e++) {
                    int src = g_srcs[e];
                    if ((unsigned)src < N_NODES) {
                        const uint4* ur = (const uint4*)&g_xpad[src * HPAD];
                        uint4 p0 = ur[0], p1 = ur[1];
                        const __half2* h0 = (const __half2*)&p0;
                        const __half2* h1 = (const __half2*)&p1;
                        #pragma unroll
                        for (int m = 0; m < 4; m++) {
                            float2 f0 = __half22float2(h0[m]);
                            a[m*2+0] += f0.x; a[m*2+1] += f0.y;
                        }
                        float2 f4 = __half22float2(h1[0]);
                        a[8] += f4.x; a[9] += f4.y;
                        float2 f5 = __half22float2(h1[1]);
                        a[10] += f5.x;
                    }
                }
                float dv = g_dinv[node];
                #pragma unroll
                for (int f = 0; f < N_FEAT; f++) a[f] *= dv;
            }
            #pragma unroll
            for (int f = 0; f < N_FEAT; f++) sxT[f][threadIdx.x] = a[f];
        }
        __syncthreads();
        for (int n0 = s * 4; n0 < cntp; n0 += 16) {
            ull d0 = bj2, d1 = bj2;
            #pragma unroll
            for (int f = 0; f < N_FEAT; f++) {
                ulonglong2 v = *(const ulonglong2*)&sxT[f][n0];
                d0 = fma2(v.x, w2[f], d0);
                d1 = fma2(v.y, w2[f], d1);
            }
            float h0, h1, h2, h3;
            unpack2(h0, h1, d0);
            unpack2(h2, h3, d1);
            acc += fmaxf(h0, 0.0f) + fmaxf(h1, 0.0f) + fmaxf(h2, 0.0f) + fmaxf(h3, 0.0f);
        }
        int padc = cntp - cnt;
        if (padc && (((cnt >> 2) & 3) == s)) padsum += padc;
    }

    acc -= (float)padsum * fmaxf(bj, 0.0f);

    red[s][j] = acc;
    __syncthreads();
    if (s == 0) {
        float tot = red[0][j] + red[1][j] + red[2][j] + red[3][j];
        atomicAdd(&g_pooled[b * HIDDEN + j], tot);
    }
}

// ---- out[b][c] = (pooled[b]/max(cnt,1)) @ W_lin + b_lin ----
__global__ void final_kernel(const float* __restrict__ Wlin,
                             const float* __restrict__ blin,
                             float* __restrict__ out) {
    int t = blockIdx.x * blockDim.x + threadIdx.x;
    if (t < BATCH * N_CLASSES) {
        int b = t / N_CLASSES, c = t % N_CLASSES;
        int cnt   = g_bnd[b + 1] - g_bnd[b];
        float inv = 1.0f / fmaxf((float)cnt, 1.0f);
        float acc = blin[c];
        #pragma unroll 8
        for (int jj = 0; jj < HIDDEN; jj++)
            acc = fmaf(g_pooled[b * HIDDEN + jj] * inv, Wlin[jj * N_CLASSES + c], acc);
        out[t] = acc;
    }
}

extern "C" void kernel_launch(void* const* d_in, const int* in_sizes, int n_in,
                              void* d_out, int out_size) {
    const float* x     = (const float*)d_in[0];
    const int*   ei    = (const int*)d_in[1];     // int64 narrowed to int32 by harness
    const int*   batch = (const int*)d_in[3];
    const float* Wc    = (const float*)d_in[4];
    const float* bc    = (const float*)d_in[5];
    const float* Wlin  = (const float*)d_in[6];
    const float* blin  = (const float*)d_in[7];
    float*       out   = (float*)d_out;

    static void* p_count  = nullptr;
    static void* p_pooled = nullptr;
    static void* p_state  = nullptr;
    static void* p_ticket = nullptr;
    static cudaStream_t s2 = nullptr;
    static cudaEvent_t  ev_fork = nullptr, ev_join = nullptr;
    if (!p_count) {
        cudaGetSymbolAddress(&p_count,  g_count);
        cudaGetSymbolAddress(&p_pooled, g_pooled);
        cudaGetSymbolAddress(&p_state,  g_state);
        cudaGetSymbolAddress(&p_ticket, g_ticket);
        cudaStreamCreateWithFlags(&s2, cudaStreamNonBlocking);
        cudaEventCreateWithFlags(&ev_fork, cudaEventDisableTiming);
        cudaEventCreateWithFlags(&ev_join, cudaEventDisableTiming);
    }

    // main stream: zero count + scan state, then hist
    cudaMemsetAsync(p_count,  0, sizeof(int) * N_NODES);
    cudaMemsetAsync(p_state,  0, sizeof(ull) * NB_SCAN);
    cudaMemsetAsync(p_ticket, 0, sizeof(int));
    hist_bnd_kernel<<<(N_EDGES / 4 + 255) / 256, 256>>>(ei, batch);

    // fork: side stream does pooled memset + dinv/xpad (depends only on counts)
    cudaEventRecord(ev_fork, 0);
    cudaStreamWaitEvent(s2, ev_fork, 0);
    cudaMemsetAsync(p_pooled, 0, sizeof(float) * BATCH * HIDDEN, s2);
    dinv_pad_kernel<<<(N_NODES + FIN_NODES - 1) / FIN_NODES, 256, 0, s2>>>(x);
    cudaEventRecord(ev_join, s2);

    // main stream: single-pass scan -> CSR fill (concurrent with dinv_pad)
    scan_kernel<<<NB_SCAN, 256>>>();
    fill_kernel<<<(N_EDGES / 4 + 255) / 256, 256>>>(ei);

    // join, then fused + final
    cudaStreamWaitEvent(0, ev_join, 0);
    fused_kernel<<<BATCH * SPLIT, 256>>>(Wc, bc);
    final_kernel<<<(BATCH * N_CLASSES + 127) / 128, 128>>>(Wlin, blin, out);
}